// round 15
// baseline (speedup 1.0000x reference)
#include <cuda_runtime.h>
#include <cuda_fp16.h>

// fp16 pyramid, levels 0..7. Texels/plane: 512^2 + 256^2 + ... + 4^2 = 349520.
#define T_ALL 349520
__device__ __half g_pyrh[3 * T_ALL * 16];     // 33.6 MB
__device__ float4 g_l4[3 * 1024 * 4];         // fp32 level 4 (32x32/plane), c4-sliced
__device__ unsigned g_ctr3[3];                // per-plane completion counters

// texel offset of level l (0..7) within a plane's fp16 region
__constant__ int c_off[8] = {0, 262144, 327680, 344064, 348160, 349184, 349440, 349504};

__device__ __forceinline__ void st_h4(__half* p, float4 v) {
    __half2 a = __floats2half2_rn(v.x, v.y);
    __half2 b = __floats2half2_rn(v.z, v.w);
    uint2 u;
    u.x = *reinterpret_cast<unsigned*>(&a);
    u.y = *reinterpret_cast<unsigned*>(&b);
    *reinterpret_cast<uint2*>(p) = u;
}

__device__ __forceinline__ float4 avg4(float4 a, float4 b, float4 c, float4 d) {
    float4 r;
    r.x = (a.x + b.x + c.x + d.x) * 0.25f;
    r.y = (a.y + b.y + c.y + d.y) * 0.25f;
    r.z = (a.z + b.z + c.z + d.z) * 0.25f;
    r.w = (a.w + b.w + c.w + d.w) * 0.25f;
    return r;
}

// ---------------------------------------------------------------------------
// ds_fused: block = (plane, 16x16 L0 tile). Coalesced fm load, fp16 L0 copy
// via STG.128, cascade L1..L4 in smem. Per-plane last block builds L5..L7.
// ---------------------------------------------------------------------------
__global__ void __launch_bounds__(256) ds_fused(const float4* __restrict__ fm) {
    __shared__ float4 s0[1024];   // 16x16 texels x 4 f4 (16KB)
    __shared__ float4 s1[256];    // 8x8
    __shared__ float4 s2[64];     // 4x4
    __shared__ float4 s3[16];     // 2x2
    __shared__ bool   isLast;

    const int b = blockIdx.x;
    const int tile = b & 1023;
    const int plane = b >> 10;
    const int tx = tile & 31, ty = tile >> 5;
    const int tid = threadIdx.x;

    const float4* src = fm + (size_t)plane * (512 * 512 * 4);
    __half* hp = g_pyrh + (size_t)plane * T_ALL * 16;

    // L0: 512 items of (row r, texel col c, half h): 2 LDG.128 + 1 STG.128.
    #pragma unroll
    for (int i = 0; i < 2; ++i) {
        int p = i * 256 + tid;
        int h = p & 1;
        int cc = (p >> 1) & 15;
        int r = p >> 5;
        int gy = ty * 16 + r, gx = tx * 16 + cc;
        const float4* sp = src + ((size_t)gy * 512 + gx) * 4 + h * 2;
        float4 v0 = __ldg(sp);
        float4 v1 = __ldg(sp + 1);
        s0[(r * 16 + cc) * 4 + h * 2]     = v0;
        s0[(r * 16 + cc) * 4 + h * 2 + 1] = v1;
        __half2 a0 = __floats2half2_rn(v0.x, v0.y);
        __half2 a1 = __floats2half2_rn(v0.z, v0.w);
        __half2 b0 = __floats2half2_rn(v1.x, v1.y);
        __half2 b1 = __floats2half2_rn(v1.z, v1.w);
        uint4 uu;
        uu.x = *reinterpret_cast<unsigned*>(&a0);
        uu.y = *reinterpret_cast<unsigned*>(&a1);
        uu.z = *reinterpret_cast<unsigned*>(&b0);
        uu.w = *reinterpret_cast<unsigned*>(&b1);
        *reinterpret_cast<uint4*>(hp + ((size_t)gy * 512 + gx) * 16 + h * 8) = uu;
    }
    __syncthreads();

    // L1: 8x8 texels x4
    {
        int c4 = tid & 3, x = (tid >> 2) & 7, y = tid >> 5;
        float4 v = avg4(s0[((2 * y) * 16 + 2 * x) * 4 + c4],
                        s0[((2 * y) * 16 + 2 * x + 1) * 4 + c4],
                        s0[((2 * y + 1) * 16 + 2 * x) * 4 + c4],
                        s0[((2 * y + 1) * 16 + 2 * x + 1) * 4 + c4]);
        s1[tid] = v;
        st_h4(hp + (size_t)(c_off[1] + (ty * 8 + y) * 256 + tx * 8 + x) * 16 + c4 * 4, v);
    }
    __syncthreads();

    // L2: 4x4 x4
    if (tid < 64) {
        int c4 = tid & 3, x = (tid >> 2) & 3, y = tid >> 4;
        float4 v = avg4(s1[((2 * y) * 8 + 2 * x) * 4 + c4],
                        s1[((2 * y) * 8 + 2 * x + 1) * 4 + c4],
                        s1[((2 * y + 1) * 8 + 2 * x) * 4 + c4],
                        s1[((2 * y + 1) * 8 + 2 * x + 1) * 4 + c4]);
        s2[tid] = v;
        st_h4(hp + (size_t)(c_off[2] + (ty * 4 + y) * 128 + tx * 4 + x) * 16 + c4 * 4, v);
    }
    __syncthreads();

    // L3: 2x2 x4
    if (tid < 16) {
        int c4 = tid & 3, x = (tid >> 2) & 1, y = tid >> 3;
        float4 v = avg4(s2[((2 * y) * 4 + 2 * x) * 4 + c4],
                        s2[((2 * y) * 4 + 2 * x + 1) * 4 + c4],
                        s2[((2 * y + 1) * 4 + 2 * x) * 4 + c4],
                        s2[((2 * y + 1) * 4 + 2 * x + 1) * 4 + c4]);
        s3[tid] = v;
        st_h4(hp + (size_t)(c_off[3] + (ty * 2 + y) * 64 + tx * 2 + x) * 16 + c4 * 4, v);
    }
    __syncthreads();

    // L4: one texel per tile
    if (tid < 4) {
        int c4 = tid;
        float4 v = avg4(s3[0 * 4 + c4], s3[1 * 4 + c4], s3[2 * 4 + c4], s3[3 * 4 + c4]);
        st_h4(hp + (size_t)(c_off[4] + ty * 32 + tx) * 16 + c4 * 4, v);
        g_l4[((size_t)plane * 1024 + ty * 32 + tx) * 4 + c4] = v;
    }

    // ---- per-plane last block builds L5..L7 from fp32 L4 ----
    if (tid == 0) {
        __threadfence();
        unsigned c = atomicAdd(&g_ctr3[plane], 1u);
        isLast = (c == 1023u);
    }
    __syncthreads();
    if (!isLast) return;
    if (tid == 0) g_ctr3[plane] = 0;   // reset for next graph replay
    __threadfence();                   // see all blocks' g_l4 writes
    __syncthreads();

    const float4* L4 = g_l4 + (size_t)plane * 1024 * 4;
    // L5: 16x16 x4 = 1024 items, staged in s0
    for (int k = tid; k < 1024; k += 256) {
        int c4 = k & 3, x = (k >> 2) & 15, y = k >> 6;
        float4 v = avg4(L4[((2 * y) * 32 + 2 * x) * 4 + c4],
                        L4[((2 * y) * 32 + 2 * x + 1) * 4 + c4],
                        L4[((2 * y + 1) * 32 + 2 * x) * 4 + c4],
                        L4[((2 * y + 1) * 32 + 2 * x + 1) * 4 + c4]);
        s0[k] = v;
        st_h4(hp + (size_t)(c_off[5] + y * 16 + x) * 16 + c4 * 4, v);
    }
    __syncthreads();
    // L6: 8x8 x4 = 256 items
    {
        int c4 = tid & 3, x = (tid >> 2) & 7, y = tid >> 5;
        float4 v = avg4(s0[((2 * y) * 16 + 2 * x) * 4 + c4],
                        s0[((2 * y) * 16 + 2 * x + 1) * 4 + c4],
                        s0[((2 * y + 1) * 16 + 2 * x) * 4 + c4],
                        s0[((2 * y + 1) * 16 + 2 * x + 1) * 4 + c4]);
        st_h4(hp + (size_t)(c_off[6] + y * 8 + x) * 16 + c4 * 4, v);
    }
    // L7: 4x4 x4 via 4x4 box of L5
    if (tid < 64) {
        int c4 = tid & 3, x = (tid >> 2) & 3, y = tid >> 4;
        float4 acc = make_float4(0.f, 0.f, 0.f, 0.f);
        #pragma unroll
        for (int dy = 0; dy < 4; ++dy)
            #pragma unroll
            for (int dx = 0; dx < 4; ++dx) {
                float4 t = s0[((4 * y + dy) * 16 + 4 * x + dx) * 4 + c4];
                acc.x += t.x; acc.y += t.y; acc.z += t.z; acc.w += t.w;
            }
        float4 v = make_float4(acc.x * 0.0625f, acc.y * 0.0625f,
                               acc.z * 0.0625f, acc.w * 0.0625f);
        st_h4(hp + (size_t)(c_off[7] + y * 4 + x) * 16 + c4 * 4, v);
    }
}

// ---------------------------------------------------------------------------
// Sample: gridDim.y = plane. 4 lanes per (point, plane); each thread handles
// TWO points (pt, pt + N/2) for 8 front-batched loads (MLP=8).
// Weights folded into the y-blend; one deferred exchange per point.
// ---------------------------------------------------------------------------
struct Prep {
    const uint4 *pa0, *pb0, *pa1, *pb1;   // 4 tap addresses
    float fx0, fy0, fx1, fy1, f;
};

__device__ __forceinline__ Prep prep_pt(float u, float v, float lvl,
                                        int cx, int c2, const uint4* pyr) {
    Prep P;
    lvl = fminf(fmaxf(lvl, 0.f), 7.f);
    const float l0f = floorf(lvl);
    P.f = lvl - l0f;
    const int l0 = (int)l0f;
    const int l1 = min(l0 + 1, 7);

    const int sz0 = 512 >> l0;
    const float px0 = fmaf(u, (float)sz0, -0.5f);
    const float py0 = fmaf(v, (float)sz0, -0.5f);
    const float x0f0 = floorf(px0), y0f0 = floorf(py0);
    P.fx0 = px0 - x0f0; P.fy0 = py0 - y0f0;
    const int xc0 = min(max((int)x0f0 + cx, 0), sz0 - 1);
    const int ya0 = max((int)y0f0, 0);
    const int yb0 = min((int)y0f0 + 1, sz0 - 1);
    const uint4* b0 = pyr + c_off[l0] * 2;
    P.pa0 = b0 + (ya0 * sz0 + xc0) * 2 + c2;
    P.pb0 = b0 + (yb0 * sz0 + xc0) * 2 + c2;

    const int sz1 = 512 >> l1;
    const float px1 = fmaf(u, (float)sz1, -0.5f);
    const float py1 = fmaf(v, (float)sz1, -0.5f);
    const float x0f1 = floorf(px1), y0f1 = floorf(py1);
    P.fx1 = px1 - x0f1; P.fy1 = py1 - y0f1;
    const int xc1 = min(max((int)x0f1 + cx, 0), sz1 - 1);
    const int ya1 = max((int)y0f1, 0);
    const int yb1 = min((int)y0f1 + 1, sz1 - 1);
    const uint4* b1 = pyr + c_off[l1] * 2;
    P.pa1 = b1 + (ya1 * sz1 + xc1) * 2 + c2;
    P.pb1 = b1 + (yb1 * sz1 + xc1) * 2 + c2;
    return P;
}

// One tap: blend rows with pre-folded weights (wa=wo*(1-fy), wb=wo*fy packed
// in one half2; lo/hi broadcast folds into SASS half-lane selectors), route
// keep/send by cx, accumulate into K (own slice) and D (partner slice).
__device__ __forceinline__ void tap_acc(uint4 ra, uint4 rb, float fy, float wo_f,
                                        int cx,
                                        __half2& K0, __half2& K1,
                                        __half2& D0, __half2& D1, bool first) {
    const float wb_f = wo_f * fy;
    const float wa_f = wo_f - wb_f;
    const __half2 wab = __floats2half2_rn(wa_f, wb_f);
    const __half2 wya = __low2half2(wab);
    const __half2 wyb = __high2half2(wab);
    __half2 h0 = __hfma2(*(const __half2*)&rb.x, wyb, __hmul2(*(const __half2*)&ra.x, wya));
    __half2 h1 = __hfma2(*(const __half2*)&rb.y, wyb, __hmul2(*(const __half2*)&ra.y, wya));
    __half2 h2 = __hfma2(*(const __half2*)&rb.z, wyb, __hmul2(*(const __half2*)&ra.z, wya));
    __half2 h3 = __hfma2(*(const __half2*)&rb.w, wyb, __hmul2(*(const __half2*)&ra.w, wya));
    const __half2 k0 = cx ? h2 : h0;
    const __half2 k1 = cx ? h3 : h1;
    const __half2 d0 = cx ? h0 : h2;
    const __half2 d1 = cx ? h1 : h3;
    if (first) {
        K0 = k0; K1 = k1; D0 = d0; D1 = d1;
    } else {
        K0 = __hadd2(K0, k0); K1 = __hadd2(K1, k1);
        D0 = __hadd2(D0, d0); D1 = __hadd2(D1, d1);
    }
}

__device__ __forceinline__ float4 finish_pt(__half2 K0, __half2 K1,
                                            __half2 D0, __half2 D1,
                                            unsigned msk) {
    unsigned d0u = *reinterpret_cast<unsigned*>(&D0);
    unsigned d1u = *reinterpret_cast<unsigned*>(&D1);
    unsigned r0u = __shfl_xor_sync(msk, d0u, 2);
    unsigned r1u = __shfl_xor_sync(msk, d1u, 2);
    __half2 s0h = __hadd2(K0, *reinterpret_cast<__half2*>(&r0u));
    __half2 s1h = __hadd2(K1, *reinterpret_cast<__half2*>(&r1u));
    float2 f01 = __half22float2(s0h);
    float2 f23 = __half22float2(s1h);
    return make_float4(f01.x, f01.y, f23.x, f23.y);
}

__global__ void __launch_bounds__(256) sample_kernel(
        const float* __restrict__ xin,
        const float* __restrict__ level,
        float4* __restrict__ out, int N) {
    const int t4 = blockIdx.x * blockDim.x + threadIdx.x;
    const int q = t4 >> 2;
    const int half = (N + 1) >> 1;
    if (q >= half) return;
    const int plane = blockIdx.y;
    const int sub = t4 & 3;
    const int c2 = sub & 1;
    const int cx = sub >> 1;
    const float one_m_fcx = 1.f - (float)cx;
    const unsigned msk = 0xFFFFFFFFu;

    const int ptA = q;
    const int ptB = q + half;
    const bool hasB = ptB < N;
    const int ptBc = hasB ? ptB : ptA;

    // quad-cooperative input loads (batched)
    const float* addrA = (sub < 3) ? (xin + ptA * 3 + sub) : (level + ptA);
    const float* addrB = (sub < 3) ? (xin + ptBc * 3 + sub) : (level + ptBc);
    const float valA = __ldg(addrA);
    const float valB = __ldg(addrB);

    const int uidx = (plane == 0) ? 1 : 0;
    const int vidx = (plane == 2) ? 1 : 2;
    const float uA = __shfl_sync(msk, valA, uidx, 4);
    const float vA = __shfl_sync(msk, valA, vidx, 4);
    const float lA = __shfl_sync(msk, valA, 3, 4);
    const float uB = __shfl_sync(msk, valB, uidx, 4);
    const float vB = __shfl_sync(msk, valB, vidx, 4);
    const float lB = __shfl_sync(msk, valB, 3, 4);

    const uint4* pyr = reinterpret_cast<const uint4*>(g_pyrh) + (size_t)plane * T_ALL * 2;

    const Prep PA = prep_pt(uA, vA, lA, cx, c2, pyr);
    const Prep PB = prep_pt(uB, vB, lB, cx, c2, pyr);

    // ---- 8 independent loads, front-batched ----
    const uint4 Aa0 = __ldg(PA.pa0);
    const uint4 Ab0 = __ldg(PA.pb0);
    const uint4 Aa1 = __ldg(PA.pa1);
    const uint4 Ab1 = __ldg(PA.pb1);
    const uint4 Ba0 = __ldg(PB.pa0);
    const uint4 Bb0 = __ldg(PB.pb0);
    const uint4 Ba1 = __ldg(PB.pa1);
    const uint4 Bb1 = __ldg(PB.pb1);

    __half2 KA0, KA1, DA0, DA1;
    __half2 KB0, KB1, DB0, DB1;
    tap_acc(Aa0, Ab0, PA.fy0, fabsf(one_m_fcx - PA.fx0) * (1.f - PA.f), cx, KA0, KA1, DA0, DA1, true);
    tap_acc(Aa1, Ab1, PA.fy1, fabsf(one_m_fcx - PA.fx1) * PA.f,         cx, KA0, KA1, DA0, DA1, false);
    tap_acc(Ba0, Bb0, PB.fy0, fabsf(one_m_fcx - PB.fx0) * (1.f - PB.f), cx, KB0, KB1, DB0, DB1, true);
    tap_acc(Ba1, Bb1, PB.fy1, fabsf(one_m_fcx - PB.fx1) * PB.f,         cx, KB0, KB1, DB0, DB1, false);

    const float4 RA = finish_pt(KA0, KA1, DA0, DA1, msk);
    const float4 RB = finish_pt(KB0, KB1, DB0, DB1, msk);

    // evict-first streaming stores (channels [c2*8 + cx*4 .. +4))
    __stcs(out + (ptA * 3 + plane) * 4 + c2 * 2 + cx, RA);
    if (hasB)
        __stcs(out + (ptB * 3 + plane) * 4 + c2 * 2 + cx, RB);
}

extern "C" void kernel_launch(void* const* d_in, const int* in_sizes, int n_in,
                              void* d_out, int out_size) {
    const float*  x     = (const float*)d_in[0];
    const float*  level = (const float*)d_in[1];
    const float4* fm    = (const float4*)d_in[2];
    float4* out = (float4*)d_out;
    const int N = in_sizes[0] / 3;
    const int half = (N + 1) >> 1;

    ds_fused<<<3 * 1024, 256>>>(fm);

    dim3 grid((half * 4 + 255) / 256, 3);
    sample_kernel<<<grid, 256>>>(x, level, out, N);
}

// round 17
// speedup vs baseline: 1.4066x; 1.4066x over previous
#include <cuda_runtime.h>
#include <cuda_fp16.h>

// fp16 pyramid, levels 0..7. Texels/plane: 512^2 + 256^2 + ... + 4^2 = 349520.
#define T_ALL 349520
__device__ __half g_pyrh[3 * T_ALL * 16];     // 33.6 MB
__device__ float4 g_l4[3 * 1024 * 4];         // fp32 level 4 (32x32/plane), c4-sliced
__device__ unsigned g_ctr3[3];                // per-plane completion counters

// texel offset of level l (0..7) within a plane's fp16 region
__constant__ int c_off[8] = {0, 262144, 327680, 344064, 348160, 349184, 349440, 349504};

__device__ __forceinline__ void st_h4(__half* p, float4 v) {
    __half2 a = __floats2half2_rn(v.x, v.y);
    __half2 b = __floats2half2_rn(v.z, v.w);
    uint2 u;
    u.x = *reinterpret_cast<unsigned*>(&a);
    u.y = *reinterpret_cast<unsigned*>(&b);
    *reinterpret_cast<uint2*>(p) = u;
}

__device__ __forceinline__ float4 avg4(float4 a, float4 b, float4 c, float4 d) {
    float4 r;
    r.x = (a.x + b.x + c.x + d.x) * 0.25f;
    r.y = (a.y + b.y + c.y + d.y) * 0.25f;
    r.z = (a.z + b.z + c.z + d.z) * 0.25f;
    r.w = (a.w + b.w + c.w + d.w) * 0.25f;
    return r;
}

// ---------------------------------------------------------------------------
// ds_fused: block = (plane, 16x16 L0 tile). Coalesced fm load, fp16 L0 copy
// via STG.128, cascade L1..L4 in smem. Per-plane last block builds L5..L7.
// ---------------------------------------------------------------------------
__global__ void __launch_bounds__(256) ds_fused(const float4* __restrict__ fm) {
    __shared__ float4 s0[1024];   // 16x16 texels x 4 f4 (16KB)
    __shared__ float4 s1[256];    // 8x8
    __shared__ float4 s2[64];     // 4x4
    __shared__ float4 s3[16];     // 2x2
    __shared__ bool   isLast;

    const int b = blockIdx.x;
    const int tile = b & 1023;
    const int plane = b >> 10;
    const int tx = tile & 31, ty = tile >> 5;
    const int tid = threadIdx.x;

    const float4* src = fm + (size_t)plane * (512 * 512 * 4);
    __half* hp = g_pyrh + (size_t)plane * T_ALL * 16;

    // L0: 512 items of (row r, texel col c, half h): 2 LDG.128 + 1 STG.128.
    #pragma unroll
    for (int i = 0; i < 2; ++i) {
        int p = i * 256 + tid;
        int h = p & 1;
        int cc = (p >> 1) & 15;
        int r = p >> 5;
        int gy = ty * 16 + r, gx = tx * 16 + cc;
        const float4* sp = src + ((size_t)gy * 512 + gx) * 4 + h * 2;
        float4 v0 = __ldg(sp);
        float4 v1 = __ldg(sp + 1);
        s0[(r * 16 + cc) * 4 + h * 2]     = v0;
        s0[(r * 16 + cc) * 4 + h * 2 + 1] = v1;
        __half2 a0 = __floats2half2_rn(v0.x, v0.y);
        __half2 a1 = __floats2half2_rn(v0.z, v0.w);
        __half2 b0 = __floats2half2_rn(v1.x, v1.y);
        __half2 b1 = __floats2half2_rn(v1.z, v1.w);
        uint4 uu;
        uu.x = *reinterpret_cast<unsigned*>(&a0);
        uu.y = *reinterpret_cast<unsigned*>(&a1);
        uu.z = *reinterpret_cast<unsigned*>(&b0);
        uu.w = *reinterpret_cast<unsigned*>(&b1);
        *reinterpret_cast<uint4*>(hp + ((size_t)gy * 512 + gx) * 16 + h * 8) = uu;
    }
    __syncthreads();

    // L1: 8x8 texels x4
    {
        int c4 = tid & 3, x = (tid >> 2) & 7, y = tid >> 5;
        float4 v = avg4(s0[((2 * y) * 16 + 2 * x) * 4 + c4],
                        s0[((2 * y) * 16 + 2 * x + 1) * 4 + c4],
                        s0[((2 * y + 1) * 16 + 2 * x) * 4 + c4],
                        s0[((2 * y + 1) * 16 + 2 * x + 1) * 4 + c4]);
        s1[tid] = v;
        st_h4(hp + (size_t)(c_off[1] + (ty * 8 + y) * 256 + tx * 8 + x) * 16 + c4 * 4, v);
    }
    __syncthreads();

    // L2: 4x4 x4
    if (tid < 64) {
        int c4 = tid & 3, x = (tid >> 2) & 3, y = tid >> 4;
        float4 v = avg4(s1[((2 * y) * 8 + 2 * x) * 4 + c4],
                        s1[((2 * y) * 8 + 2 * x + 1) * 4 + c4],
                        s1[((2 * y + 1) * 8 + 2 * x) * 4 + c4],
                        s1[((2 * y + 1) * 8 + 2 * x + 1) * 4 + c4]);
        s2[tid] = v;
        st_h4(hp + (size_t)(c_off[2] + (ty * 4 + y) * 128 + tx * 4 + x) * 16 + c4 * 4, v);
    }
    __syncthreads();

    // L3: 2x2 x4
    if (tid < 16) {
        int c4 = tid & 3, x = (tid >> 2) & 1, y = tid >> 3;
        float4 v = avg4(s2[((2 * y) * 4 + 2 * x) * 4 + c4],
                        s2[((2 * y) * 4 + 2 * x + 1) * 4 + c4],
                        s2[((2 * y + 1) * 4 + 2 * x) * 4 + c4],
                        s2[((2 * y + 1) * 4 + 2 * x + 1) * 4 + c4]);
        s3[tid] = v;
        st_h4(hp + (size_t)(c_off[3] + (ty * 2 + y) * 64 + tx * 2 + x) * 16 + c4 * 4, v);
    }
    __syncthreads();

    // L4: one texel per tile
    if (tid < 4) {
        int c4 = tid;
        float4 v = avg4(s3[0 * 4 + c4], s3[1 * 4 + c4], s3[2 * 4 + c4], s3[3 * 4 + c4]);
        st_h4(hp + (size_t)(c_off[4] + ty * 32 + tx) * 16 + c4 * 4, v);
        g_l4[((size_t)plane * 1024 + ty * 32 + tx) * 4 + c4] = v;
    }

    // ---- per-plane last block builds L5..L7 from fp32 L4 ----
    if (tid == 0) {
        __threadfence();
        unsigned c = atomicAdd(&g_ctr3[plane], 1u);
        isLast = (c == 1023u);
    }
    __syncthreads();
    if (!isLast) return;
    if (tid == 0) g_ctr3[plane] = 0;   // reset for next graph replay
    __threadfence();                   // see all blocks' g_l4 writes
    __syncthreads();

    const float4* L4 = g_l4 + (size_t)plane * 1024 * 4;
    // L5: 16x16 x4 = 1024 items, staged in s0
    for (int k = tid; k < 1024; k += 256) {
        int c4 = k & 3, x = (k >> 2) & 15, y = k >> 6;
        float4 v = avg4(L4[((2 * y) * 32 + 2 * x) * 4 + c4],
                        L4[((2 * y) * 32 + 2 * x + 1) * 4 + c4],
                        L4[((2 * y + 1) * 32 + 2 * x) * 4 + c4],
                        L4[((2 * y + 1) * 32 + 2 * x + 1) * 4 + c4]);
        s0[k] = v;
        st_h4(hp + (size_t)(c_off[5] + y * 16 + x) * 16 + c4 * 4, v);
    }
    __syncthreads();
    // L6: 8x8 x4 = 256 items
    {
        int c4 = tid & 3, x = (tid >> 2) & 7, y = tid >> 5;
        float4 v = avg4(s0[((2 * y) * 16 + 2 * x) * 4 + c4],
                        s0[((2 * y) * 16 + 2 * x + 1) * 4 + c4],
                        s0[((2 * y + 1) * 16 + 2 * x) * 4 + c4],
                        s0[((2 * y + 1) * 16 + 2 * x + 1) * 4 + c4]);
        st_h4(hp + (size_t)(c_off[6] + y * 8 + x) * 16 + c4 * 4, v);
    }
    // L7: 4x4 x4 via 4x4 box of L5
    if (tid < 64) {
        int c4 = tid & 3, x = (tid >> 2) & 3, y = tid >> 4;
        float4 acc = make_float4(0.f, 0.f, 0.f, 0.f);
        #pragma unroll
        for (int dy = 0; dy < 4; ++dy)
            #pragma unroll
            for (int dx = 0; dx < 4; ++dx) {
                float4 t = s0[((4 * y + dy) * 16 + 4 * x + dx) * 4 + c4];
                acc.x += t.x; acc.y += t.y; acc.z += t.z; acc.w += t.w;
            }
        float4 v = make_float4(acc.x * 0.0625f, acc.y * 0.0625f,
                               acc.z * 0.0625f, acc.w * 0.0625f);
        st_h4(hp + (size_t)(c_off[7] + y * 4 + x) * 16 + c4 * 4, v);
    }
}

// ---------------------------------------------------------------------------
// Sample: gridDim.y = plane. 4 lanes per (point, plane); each thread handles
// TWO points (pt, pt + N/2) for 8 front-batched loads (MLP=8).
// ---------------------------------------------------------------------------
struct Prep {
    const uint4 *pa0, *pb0, *pa1, *pb1;   // 4 tap addresses
    float fx0, fy0, fx1, fy1, f;
};

__device__ __forceinline__ Prep prep_pt(float u, float v, float lvl,
                                        int cx, int c2, const uint4* pyr) {
    Prep P;
    lvl = fminf(fmaxf(lvl, 0.f), 7.f);
    const float l0f = floorf(lvl);
    P.f = lvl - l0f;
    const int l0 = (int)l0f;
    const int l1 = min(l0 + 1, 7);

    const int sz0 = 512 >> l0;
    const float px0 = fmaf(u, (float)sz0, -0.5f);
    const float py0 = fmaf(v, (float)sz0, -0.5f);
    const float x0f0 = floorf(px0), y0f0 = floorf(py0);
    P.fx0 = px0 - x0f0; P.fy0 = py0 - y0f0;
    const int xc0 = min(max((int)x0f0 + cx, 0), sz0 - 1);
    const int ya0 = max((int)y0f0, 0);
    const int yb0 = min((int)y0f0 + 1, sz0 - 1);
    const uint4* b0 = pyr + c_off[l0] * 2;
    P.pa0 = b0 + (ya0 * sz0 + xc0) * 2 + c2;
    P.pb0 = b0 + (yb0 * sz0 + xc0) * 2 + c2;

    const int sz1 = 512 >> l1;
    const float px1 = fmaf(u, (float)sz1, -0.5f);
    const float py1 = fmaf(v, (float)sz1, -0.5f);
    const float x0f1 = floorf(px1), y0f1 = floorf(py1);
    P.fx1 = px1 - x0f1; P.fy1 = py1 - y0f1;
    const int xc1 = min(max((int)x0f1 + cx, 0), sz1 - 1);
    const int ya1 = max((int)y0f1, 0);
    const int yb1 = min((int)y0f1 + 1, sz1 - 1);
    const uint4* b1 = pyr + c_off[l1] * 2;
    P.pa1 = b1 + (ya1 * sz1 + xc1) * 2 + c2;
    P.pb1 = b1 + (yb1 * sz1 + xc1) * 2 + c2;
    return P;
}

// One tap: row blend in half2, pre-weight, exchange with partner lane, add.
__device__ __forceinline__ void tap_acc(uint4 ra, uint4 rb, float fy, float wo_f,
                                        int cx, unsigned msk, float4& R, bool first) {
    const __half2 wya = __float2half2_rn(1.f - fy);
    const __half2 wyb = __float2half2_rn(fy);
    __half2 h0 = __hfma2(*(const __half2*)&rb.x, wyb, __hmul2(*(const __half2*)&ra.x, wya));
    __half2 h1 = __hfma2(*(const __half2*)&rb.y, wyb, __hmul2(*(const __half2*)&ra.y, wya));
    __half2 h2 = __hfma2(*(const __half2*)&rb.z, wyb, __hmul2(*(const __half2*)&ra.z, wya));
    __half2 h3 = __hfma2(*(const __half2*)&rb.w, wyb, __hmul2(*(const __half2*)&ra.w, wya));
    const __half2 woh = __float2half2_rn(wo_f);
    h0 = __hmul2(h0, woh);
    h1 = __hmul2(h1, woh);
    h2 = __hmul2(h2, woh);
    h3 = __hmul2(h3, woh);
    unsigned send0 = cx ? *(unsigned*)&h0 : *(unsigned*)&h2;
    unsigned send1 = cx ? *(unsigned*)&h1 : *(unsigned*)&h3;
    unsigned keep0 = cx ? *(unsigned*)&h2 : *(unsigned*)&h0;
    unsigned keep1 = cx ? *(unsigned*)&h3 : *(unsigned*)&h1;
    unsigned recv0 = __shfl_xor_sync(msk, send0, 2);
    unsigned recv1 = __shfl_xor_sync(msk, send1, 2);
    __half2 s0h = __hadd2(*(__half2*)&keep0, *(__half2*)&recv0);
    __half2 s1h = __hadd2(*(__half2*)&keep1, *(__half2*)&recv1);
    float2 f01 = __half22float2(s0h);
    float2 f23 = __half22float2(s1h);
    if (first) {
        R = make_float4(f01.x, f01.y, f23.x, f23.y);
    } else {
        R.x += f01.x; R.y += f01.y; R.z += f23.x; R.w += f23.y;
    }
}

__global__ void __launch_bounds__(256) sample_kernel(
        const float* __restrict__ xin,
        const float* __restrict__ level,
        float4* __restrict__ out, int N) {
    const int t4 = blockIdx.x * blockDim.x + threadIdx.x;
    const int q = t4 >> 2;
    const int half = (N + 1) >> 1;
    if (q >= half) return;
    const int plane = blockIdx.y;
    const int sub = t4 & 3;
    const int c2 = sub & 1;
    const int cx = sub >> 1;
    const float one_m_fcx = 1.f - (float)cx;
    const unsigned msk = 0xFFFFFFFFu;

    const int ptA = q;
    const int ptB = q + half;
    const bool hasB = ptB < N;
    const int ptBc = hasB ? ptB : ptA;

    // quad-cooperative input loads (batched)
    const float* addrA = (sub < 3) ? (xin + ptA * 3 + sub) : (level + ptA);
    const float* addrB = (sub < 3) ? (xin + ptBc * 3 + sub) : (level + ptBc);
    const float valA = __ldg(addrA);
    const float valB = __ldg(addrB);

    const int uidx = (plane == 0) ? 1 : 0;
    const int vidx = (plane == 2) ? 1 : 2;
    const float uA = __shfl_sync(msk, valA, uidx, 4);
    const float vA = __shfl_sync(msk, valA, vidx, 4);
    const float lA = __shfl_sync(msk, valA, 3, 4);
    const float uB = __shfl_sync(msk, valB, uidx, 4);
    const float vB = __shfl_sync(msk, valB, vidx, 4);
    const float lB = __shfl_sync(msk, valB, 3, 4);

    const uint4* pyr = reinterpret_cast<const uint4*>(g_pyrh) + (size_t)plane * T_ALL * 2;

    const Prep PA = prep_pt(uA, vA, lA, cx, c2, pyr);
    const Prep PB = prep_pt(uB, vB, lB, cx, c2, pyr);

    // ---- 8 independent loads, front-batched ----
    const uint4 Aa0 = __ldg(PA.pa0);
    const uint4 Ab0 = __ldg(PA.pb0);
    const uint4 Aa1 = __ldg(PA.pa1);
    const uint4 Ab1 = __ldg(PA.pb1);
    const uint4 Ba0 = __ldg(PB.pa0);
    const uint4 Bb0 = __ldg(PB.pb0);
    const uint4 Ba1 = __ldg(PB.pa1);
    const uint4 Bb1 = __ldg(PB.pb1);

    float4 RA, RB;
    tap_acc(Aa0, Ab0, PA.fy0, fabsf(one_m_fcx - PA.fx0) * (1.f - PA.f), cx, msk, RA, true);
    tap_acc(Aa1, Ab1, PA.fy1, fabsf(one_m_fcx - PA.fx1) * PA.f,         cx, msk, RA, false);
    tap_acc(Ba0, Bb0, PB.fy0, fabsf(one_m_fcx - PB.fx0) * (1.f - PB.f), cx, msk, RB, true);
    tap_acc(Ba1, Bb1, PB.fy1, fabsf(one_m_fcx - PB.fx1) * PB.f,         cx, msk, RB, false);

    // evict-first streaming stores (channels [c2*8 + cx*4 .. +4))
    __stcs(out + (ptA * 3 + plane) * 4 + c2 * 2 + cx, RA);
    if (hasB)
        __stcs(out + (ptB * 3 + plane) * 4 + c2 * 2 + cx, RB);
}

extern "C" void kernel_launch(void* const* d_in, const int* in_sizes, int n_in,
                              void* d_out, int out_size) {
    const float*  x     = (const float*)d_in[0];
    const float*  level = (const float*)d_in[1];
    const float4* fm    = (const float4*)d_in[2];
    float4* out = (float4*)d_out;
    const int N = in_sizes[0] / 3;
    const int half = (N + 1) >> 1;

    ds_fused<<<3 * 1024, 256>>>(fm);

    dim3 grid((half * 4 + 255) / 256, 3);
    sample_kernel<<<grid, 256>>>(x, level, out, N);
}